// round 16
// baseline (speedup 1.0000x reference)
#include <cuda_runtime.h>
#include <cuda_fp16.h>
#include <cstdint>

// ---------------------------------------------------------------- constants
#define B_     64
#define T_     16
#define IMG_   84
#define FR_    7056         // 84*84
#define P_     7
#define NS_    144
#define K_     98
#define KP_    128          // physical row width (halves)
#define KSTEPS 6            // tensor path: 6 x k16 = 96; k=96,97 via FFMA
#define E_     1024
#define NTOK_  1152
#define M_     73728

// Swizzled scratch: within each 128-half row, 16B chunk c lives at c ^ (row&7).
__device__ __half g_A[(size_t)M_ * KP_];   // [m][128]  18.9 MB
__device__ __half g_B[(size_t)E_ * KP_];   // [e][128]  256 KB

// ---------------------------------------------------------------- helpers
__device__ __forceinline__ void mma_f16(float4& d, const uint32_t a[4],
                                        const uint32_t b[2]) {
    asm("mma.sync.aligned.m16n8k16.row.col.f32.f16.f16.f32 "
        "{%0,%1,%2,%3}, {%4,%5,%6,%7}, {%8,%9}, {%0,%1,%2,%3};"
        : "+f"(d.x), "+f"(d.y), "+f"(d.z), "+f"(d.w)
        : "r"(a[0]), "r"(a[1]), "r"(a[2]), "r"(a[3]), "r"(b[0]), "r"(b[1]));
}
__device__ __forceinline__ void ldsm_x4(uint32_t a[4], uint32_t addr) {
    asm volatile("ldmatrix.sync.aligned.m8n8.x4.shared.b16 {%0,%1,%2,%3}, [%4];"
                 : "=r"(a[0]), "=r"(a[1]), "=r"(a[2]), "=r"(a[3]) : "r"(addr));
}
__device__ __forceinline__ uint32_t smem_u32(const void* p) {
    uint32_t a;
    asm("{ .reg .u64 t; cvta.to.shared.u64 t, %1; cvt.u32.u64 %0, t; }"
        : "=r"(a) : "l"(p));
    return a;
}
#define MBAR_INIT(mb, c) \
    asm volatile("mbarrier.init.shared.b64 [%0], %1;" \
                 :: "r"((uint32_t)(mb)), "r"((uint32_t)(c)) : "memory")
#define MBAR_EXPECT_TX(mb, n) \
    asm volatile("mbarrier.arrive.expect_tx.shared.b64 _, [%0], %1;" \
                 :: "r"((uint32_t)(mb)), "r"((uint32_t)(n)) : "memory")
#define MBAR_WAIT(mb, ph) do {                                                    \
    uint32_t _mb = (uint32_t)(mb); uint32_t _ph = (uint32_t)(ph); uint32_t _done; \
    asm volatile("{\n\t.reg .pred p;\n\t"                                         \
        "mbarrier.try_wait.parity.acquire.cta.shared::cta.b64 p, [%1], %2;\n\t"   \
        "selp.b32 %0, 1, 0, p;\n\t}" : "=r"(_done) : "r"(_mb), "r"(_ph) : "memory"); \
    if (!_done) {                                                                 \
        asm volatile("{\n\t.reg .pred P1;\n\t"                                    \
            "WL_%=:\n\t"                                                          \
            "mbarrier.try_wait.parity.acquire.cta.shared::cta.b64 P1, [%0], %1, 0x989680;\n\t" \
            "@P1 bra.uni WD_%=;\n\t"                                              \
            "bra.uni WL_%=;\n\t"                                                  \
            "WD_%=:\n\t}" :: "r"(_mb), "r"(_ph) : "memory");                      \
    }                                                                             \
} while (0)
__device__ __forceinline__ void bulk_g2s(uint32_t dst, const void* src,
                                         uint32_t bytes, uint32_t mbar) {
    asm volatile(
        "cp.async.bulk.shared::cta.global.mbarrier::complete_tx::bytes "
        "[%0], [%1], %2, [%3];"
        :: "r"(dst), "l"(src), "r"(bytes), "r"(mbar) : "memory");
}

// ---------------------------------------------------------------- prep
#define GROWS 42
#define GHALF (GROWS * IMG_)   // 3528 pixels
__global__ void prep_kernel(const float* __restrict__ video,
                            const float* __restrict__ W) {
    int blk = blockIdx.x;
    if (blk >= 1024) {                        // ---- W conversion ----
        for (int idx = (blk - 1024) * 256 + threadIdx.x; idx < E_ * K_;
             idx += 32 * 256) {
            int e = idx / K_, k = idx - e * K_;
            int ph = (((k >> 3) ^ (e & 7)) << 3) | (k & 7);
            g_B[(size_t)e * KP_ + ph] = __float2half_rn(W[idx]);
        }
        return;
    }
    // ---- gather ----
    extern __shared__ __half fr[];            // [2][GHALF]
    int b = blk >> 4, dh = blk & 15;
    int d = dh >> 1, half = dh & 1;
    const float* src = video + (size_t)(b * T_ + d * 2) * FR_ + half * GHALF;
    for (int i = threadIdx.x; i < (2 * GHALF) / 4; i += blockDim.x) {
        int f = i / (GHALF / 4);
        int j = i - f * (GHALF / 4);
        float4 v = *(const float4*)(src + (size_t)f * FR_ + j * 4);
        __half h[4] = {__float2half_rn(v.x), __float2half_rn(v.y),
                       __float2half_rn(v.z), __float2half_rn(v.w)};
        *(uint2*)(&fr[f * GHALF + j * 4]) = *(const uint2*)h;
    }
    __syncthreads();

    int mbase = b * NTOK_ + d * NS_;
    for (int u = threadIdx.x; u < 72 * 13; u += blockDim.x) {
        int sl = u / 13, c = u - sl * 13;
        int s  = half * 72 + sl;
        int hl = sl / 12, w = sl - hl * 12;
        const __half* f0 = fr + hl * (P_ * IMG_) + w * P_;
        __half hv[8];
#pragma unroll
        for (int j = 0; j < 8; ++j) {
            int kk = c * 8 + j;
            __half v = __ushort_as_half((unsigned short)0);
            if (kk < K_) {
                int ts = kk >= 49;
                int k  = kk - ts * 49;
                int pi = k / P_, pj = k - pi * P_;
                v = f0[ts * GHALF + pi * IMG_ + pj];
            }
            hv[j] = v;
        }
        int ph = c ^ (s & 7);
        *(uint4*)(&g_A[(size_t)(mbase + s) * KP_ + ph * 8]) = *(const uint4*)hv;
    }
}

// ---------------------------------------------------------------- GEMM
// Persistent-strip GEMM: grid 8(e) x 18(strips). 512 threads = 16 warps of
// 64x32 -> 4 warps/SMSP for latency hiding (acc 4x4 = 64 regs). B loaded
// once; 16 m-tiles of 256x128 double-buffered via bulk copies; ldmatrix
// fragments; K=96 tensor + FFMA tail; direct float2 epilogue.
#define MT      256
#define ET      128
#define TILES   16
#define SBB     (ET * KP_)              // B halves (32 KB)
#define SAB     (MT * KP_)              // A halves per buffer (64 KB)
#define ATILE_BYTES (SAB * 2)
#define SMEM_BYTES ((SBB + 2 * SAB) * 2)   // 163840 B

__global__ __launch_bounds__(512, 1)
void gemm_kernel(const float* __restrict__ bias,
                 const float* __restrict__ pos,
                 float* __restrict__ out) {
    extern __shared__ __half sm[];
    __half* sB = sm;                   // [128][128] swizzled rows
    __half* sA0 = sm + SBB;
    __half* sA1 = sA0 + SAB;
    __shared__ __align__(8) unsigned long long bars[3];  // B, A0, A1

    const int tid  = threadIdx.x;
    const int lane = tid & 31;
    const int wid  = tid >> 5;         // 0..15
    const int grp  = lane >> 2;        // 0..7
    const int tg   = lane & 3;         // 0..3
    const int wm   = wid & 3;          // m-quarter  -> wm*64
    const int wn   = wid >> 2;         // e-quarter  -> wn*32

    const int e0 = blockIdx.x * ET;
    const int j0 = blockIdx.y * TILES;

    const uint32_t barB  = smem_u32(&bars[0]);
    const uint32_t barA0 = smem_u32(&bars[1]);
    const uint32_t barA1 = smem_u32(&bars[2]);

    if (tid == 0) {
        MBAR_INIT(barB, 1);
        MBAR_INIT(barA0, 1);
        MBAR_INIT(barA1, 1);
    }
    __syncthreads();

    if (tid == 0) {
        MBAR_EXPECT_TX(barB, SBB * 2);
        bulk_g2s(smem_u32(sB), g_B + (size_t)e0 * KP_, SBB * 2, barB);
        MBAR_EXPECT_TX(barA0, ATILE_BYTES);
        bulk_g2s(smem_u32(sA0), g_A + (size_t)j0 * MT * KP_, ATILE_BYTES, barA0);
        MBAR_EXPECT_TX(barA1, ATILE_BYTES);
        bulk_g2s(smem_u32(sA1), g_A + (size_t)(j0 + 1) * MT * KP_, ATILE_BYTES, barA1);
    }

    // ldmatrix per-lane address components
    const int aql  = lane & 7;
    const int aqm  = ((lane >> 3) & 1) * 8;
    const int akc  = lane >> 4;                  // A k8-chunk 0/1
    const uint32_t arl16 = (uint32_t)aql << 4;
    // B x4: rows nf2*16 + {0..7|8..15}, k-chunks 0/1 (covers 2 nf per load)
    const uint32_t uB4 = smem_u32(sB) +
        (uint32_t)(wn * 32 + ((lane >> 4) & 1) * 8 + (lane & 7)) * (KP_ * 2);
    const int bkc4 = (lane >> 3) & 1;
    const uint32_t brl16 = (uint32_t)(lane & 7) << 4;

    MBAR_WAIT(barB, 0);

#pragma unroll 1
    for (int i = 0; i < TILES; ++i) {
        const int buf = i & 1;
        const uint32_t barA = buf ? barA1 : barA0;
        __half* sA = buf ? sA1 : sA0;
        MBAR_WAIT(barA, (i >> 1) & 1);

        const int m0 = (j0 + i) * MT;
        const int n0 = m0 % NTOK_;
        const __half* wAp = sA + (wm * 64 + grp) * KP_;    // FFMA-tail A ptr
        const uint32_t uA = smem_u32(sA) +
            (uint32_t)(wm * 64 + aqm + aql) * (KP_ * 2);

        // A operands for the k=96,97 FFMA tail (chunk 12)
        float2 ca0[4], ca1[4];
        {
            const int ca = (12 ^ grp) << 3;
#pragma unroll
            for (int mf = 0; mf < 4; ++mf) {
                ca0[mf] = __half22float2(*(const __half2*)(wAp + mf * 16 * KP_ + ca));
                ca1[mf] = __half22float2(*(const __half2*)(wAp + (mf * 16 + 8) * KP_ + ca));
            }
        }

        float4 acc[4][4];
#pragma unroll
        for (int a = 0; a < 4; ++a)
#pragma unroll
            for (int b = 0; b < 4; ++b) acc[a][b] = make_float4(0.f, 0.f, 0.f, 0.f);

#pragma unroll
        for (int ks = 0; ks < KSTEPS; ++ks) {
            const uint32_t offA = (uint32_t)((2 * ks + akc) << 4) ^ arl16;
            const uint32_t offB = (uint32_t)((2 * ks + bkc4) << 4) ^ brl16;

            uint32_t af[4][4], bf[4][2];
#pragma unroll
            for (int mf = 0; mf < 4; ++mf)
                ldsm_x4(af[mf], uA + (uint32_t)mf * (16 * KP_ * 2) + offA);
#pragma unroll
            for (int nf2 = 0; nf2 < 2; ++nf2) {
                uint32_t r4[4];
                ldsm_x4(r4, uB4 + (uint32_t)nf2 * (16 * KP_ * 2) + offB);
                bf[nf2 * 2][0]     = r4[0];
                bf[nf2 * 2][1]     = r4[1];
                bf[nf2 * 2 + 1][0] = r4[2];
                bf[nf2 * 2 + 1][1] = r4[3];
            }
#pragma unroll
            for (int mf = 0; mf < 4; ++mf)
#pragma unroll
                for (int nf = 0; nf < 4; ++nf)
                    mma_f16(acc[mf][nf], af[mf], bf[nf]);
        }

        // FFMA tail: kk = 96,97 on the fp32 pipe
#pragma unroll
        for (int nf = 0; nf < 4; ++nf) {
            int er = wn * 32 + nf * 8 + 2 * tg;
            const __half* bp0 = sB + (size_t)er * KP_ + ((12 ^ (er & 7)) << 3);
            const __half* bp1 = sB + (size_t)(er + 1) * KP_ + ((12 ^ ((er + 1) & 7)) << 3);
            float2 b0 = __half22float2(*(const __half2*)bp0);
            float2 b1 = __half22float2(*(const __half2*)bp1);
#pragma unroll
            for (int mf = 0; mf < 4; ++mf) {
                float4& a = acc[mf][nf];
                a.x += ca0[mf].x * b0.x + ca0[mf].y * b0.y;
                a.y += ca0[mf].x * b1.x + ca0[mf].y * b1.y;
                a.z += ca1[mf].x * b0.x + ca1[mf].y * b0.y;
                a.w += ca1[mf].x * b1.x + ca1[mf].y * b1.y;
            }
        }

        // epilogue: out = acc + bias + pos (direct float2 stores)
        const int colb = e0 + wn * 32 + tg * 2;
#pragma unroll
        for (int mf = 0; mf < 4; ++mf) {
            int rl = wm * 64 + mf * 16 + grp;
            int m  = m0 + rl;
            int n  = n0 + rl;      if (n  >= NTOK_) n  -= NTOK_;
            int n2 = n0 + rl + 8;  if (n2 >= NTOK_) n2 -= NTOK_;
            const float* pr0 = pos + (size_t)n  * E_ + colb;
            const float* pr1 = pos + (size_t)n2 * E_ + colb;
            float* or0 = out + (size_t)m * E_ + colb;
            float* or1 = or0 + 8 * E_;
#pragma unroll
            for (int nf = 0; nf < 4; ++nf) {
                float2 bb = *(const float2*)(bias + colb + nf * 8);
                float2 p0 = *(const float2*)(pr0 + nf * 8);
                float2 p1 = *(const float2*)(pr1 + nf * 8);
                float4 a  = acc[mf][nf];
                float2 o0 = make_float2(a.x + bb.x + p0.x, a.y + bb.y + p0.y);
                float2 o1 = make_float2(a.z + bb.x + p1.x, a.w + bb.y + p1.y);
                __stcs((float2*)(or0 + nf * 8), o0);
                __stcs((float2*)(or1 + nf * 8), o1);
            }
        }

        // all reads of buffer `buf` done -> refill it 2 tiles ahead
        __syncthreads();
        if (tid == 0 && i + 2 < TILES) {
            MBAR_EXPECT_TX(barA, ATILE_BYTES);
            bulk_g2s(smem_u32(sA), g_A + (size_t)(j0 + i + 2) * MT * KP_,
                     ATILE_BYTES, barA);
        }
    }
}

// ---------------------------------------------------------------- launch
extern "C" void kernel_launch(void* const* d_in, const int* in_sizes, int n_in,
                              void* d_out, int out_size) {
    const float* video = (const float*)d_in[0];   // [64,16,1,84,84]
    const float* W     = (const float*)d_in[1];   // [1024,98]
    const float* bias  = (const float*)d_in[2];   // [1024]
    const float* pos   = (const float*)d_in[3];   // [1,1152,1024]
    float* out         = (float*)d_out;           // [64,1152,1024]

    cudaFuncSetAttribute(gemm_kernel, cudaFuncAttributeMaxDynamicSharedMemorySize,
                         SMEM_BYTES);
    cudaFuncSetAttribute(prep_kernel, cudaFuncAttributeMaxDynamicSharedMemorySize,
                         2 * GHALF * 2);

    prep_kernel<<<1024 + 32, 256, 2 * GHALF * 2>>>(video, W);
    gemm_kernel<<<dim3(E_ / ET, M_ / (MT * TILES)), 512, SMEM_BYTES>>>(bias, pos, out);
}

// round 17
// speedup vs baseline: 1.0561x; 1.0561x over previous
#include <cuda_runtime.h>
#include <cuda_fp16.h>
#include <cstdint>

// ---------------------------------------------------------------- constants
#define B_     64
#define T_     16
#define IMG_   84
#define FR_    7056         // 84*84
#define P_     7
#define NS_    144
#define K_     98
#define KP_    128          // physical row width (halves)
#define KSTEPS 7            // 7 x k16 = 112; chunks 12..13 are zero padding
#define E_     1024
#define NTOK_  1152
#define M_     73728

// Swizzled scratch: within each 128-half row, 16B chunk c lives at c ^ (row&7).
// Zero-init device globals; chunks >= 13 (and tail of 12) never written.
__device__ __half g_A[(size_t)M_ * KP_];   // [m][128]  18.9 MB
__device__ __half g_B[(size_t)E_ * KP_];   // [e][128]  256 KB

// ---------------------------------------------------------------- helpers
__device__ __forceinline__ void mma_f16(float4& d, const uint32_t a[4],
                                        const uint32_t b[2]) {
    asm("mma.sync.aligned.m16n8k16.row.col.f32.f16.f16.f32 "
        "{%0,%1,%2,%3}, {%4,%5,%6,%7}, {%8,%9}, {%0,%1,%2,%3};"
        : "+f"(d.x), "+f"(d.y), "+f"(d.z), "+f"(d.w)
        : "r"(a[0]), "r"(a[1]), "r"(a[2]), "r"(a[3]), "r"(b[0]), "r"(b[1]));
}
__device__ __forceinline__ void ldsm_x4(uint32_t a[4], uint32_t addr) {
    asm volatile("ldmatrix.sync.aligned.m8n8.x4.shared.b16 {%0,%1,%2,%3}, [%4];"
                 : "=r"(a[0]), "=r"(a[1]), "=r"(a[2]), "=r"(a[3]) : "r"(addr));
}
__device__ __forceinline__ uint32_t smem_u32(const void* p) {
    uint32_t a;
    asm("{ .reg .u64 t; cvta.to.shared.u64 t, %1; cvt.u32.u64 %0, t; }"
        : "=r"(a) : "l"(p));
    return a;
}
#define MBAR_INIT(mb, c) \
    asm volatile("mbarrier.init.shared.b64 [%0], %1;" \
                 :: "r"((uint32_t)(mb)), "r"((uint32_t)(c)) : "memory")
#define MBAR_EXPECT_TX(mb, n) \
    asm volatile("mbarrier.arrive.expect_tx.shared.b64 _, [%0], %1;" \
                 :: "r"((uint32_t)(mb)), "r"((uint32_t)(n)) : "memory")
#define MBAR_WAIT(mb, ph) do {                                                    \
    uint32_t _mb = (uint32_t)(mb); uint32_t _ph = (uint32_t)(ph); uint32_t _done; \
    asm volatile("{\n\t.reg .pred p;\n\t"                                         \
        "mbarrier.try_wait.parity.acquire.cta.shared::cta.b64 p, [%1], %2;\n\t"   \
        "selp.b32 %0, 1, 0, p;\n\t}" : "=r"(_done) : "r"(_mb), "r"(_ph) : "memory"); \
    if (!_done) {                                                                 \
        asm volatile("{\n\t.reg .pred P1;\n\t"                                    \
            "WL_%=:\n\t"                                                          \
            "mbarrier.try_wait.parity.acquire.cta.shared::cta.b64 P1, [%0], %1, 0x989680;\n\t" \
            "@P1 bra.uni WD_%=;\n\t"                                              \
            "bra.uni WL_%=;\n\t"                                                  \
            "WD_%=:\n\t}" :: "r"(_mb), "r"(_ph) : "memory");                      \
    }                                                                             \
} while (0)
__device__ __forceinline__ void bulk_g2s(uint32_t dst, const void* src,
                                         uint32_t bytes, uint32_t mbar) {
    asm volatile(
        "cp.async.bulk.shared::cta.global.mbarrier::complete_tx::bytes "
        "[%0], [%1], %2, [%3];"
        :: "r"(dst), "l"(src), "r"(bytes), "r"(mbar) : "memory");
}

// ---------------------------------------------------------------- prep
#define GROWS 42
#define GHALF (GROWS * IMG_)   // 3528 pixels
__global__ void prep_kernel(const float* __restrict__ video,
                            const float* __restrict__ W) {
    int blk = blockIdx.x;
    if (blk >= 1024) {                        // ---- W conversion ----
        for (int idx = (blk - 1024) * 256 + threadIdx.x; idx < E_ * K_;
             idx += 32 * 256) {
            int e = idx / K_, k = idx - e * K_;
            int ph = (((k >> 3) ^ (e & 7)) << 3) | (k & 7);
            g_B[(size_t)e * KP_ + ph] = __float2half_rn(W[idx]);
        }
        return;
    }
    // ---- gather ----
    extern __shared__ __half fr[];            // [2][GHALF]
    int b = blk >> 4, dh = blk & 15;
    int d = dh >> 1, half = dh & 1;
    const float* src = video + (size_t)(b * T_ + d * 2) * FR_ + half * GHALF;
    for (int i = threadIdx.x; i < (2 * GHALF) / 4; i += blockDim.x) {
        int f = i / (GHALF / 4);
        int j = i - f * (GHALF / 4);
        float4 v = *(const float4*)(src + (size_t)f * FR_ + j * 4);
        __half h[4] = {__float2half_rn(v.x), __float2half_rn(v.y),
                       __float2half_rn(v.z), __float2half_rn(v.w)};
        *(uint2*)(&fr[f * GHALF + j * 4]) = *(const uint2*)h;
    }
    __syncthreads();

    int mbase = b * NTOK_ + d * NS_;
    for (int u = threadIdx.x; u < 72 * 13; u += blockDim.x) {
        int sl = u / 13, c = u - sl * 13;
        int s  = half * 72 + sl;
        int hl = sl / 12, w = sl - hl * 12;
        const __half* f0 = fr + hl * (P_ * IMG_) + w * P_;
        __half hv[8];
#pragma unroll
        for (int j = 0; j < 8; ++j) {
            int kk = c * 8 + j;
            __half v = __ushort_as_half((unsigned short)0);
            if (kk < K_) {
                int ts = kk >= 49;
                int k  = kk - ts * 49;
                int pi = k / P_, pj = k - pi * P_;
                v = f0[ts * GHALF + pi * IMG_ + pj];
            }
            hv[j] = v;
        }
        int ph = c ^ (s & 7);
        *(uint4*)(&g_A[(size_t)(mbase + s) * KP_ + ph * 8]) = *(const uint4*)hv;
    }
}

// ---------------------------------------------------------------- GEMM
// Persistent-strip GEMM: grid 8(e) x 18(strips). 512 threads = 16 warps of
// 64x32 -> 4 warps/SMSP. Pure tensor path (KSTEPS=7, zero-padded K tail),
// no FFMA tail -> acc 64 + frags 24 + bias 8 + addr ~20 regs: no spills.
#define MT      256
#define ET      128
#define TILES   16
#define SBB     (ET * KP_)              // B halves (32 KB)
#define SAB     (MT * KP_)              // A halves per buffer (64 KB)
#define ATILE_BYTES (SAB * 2)
#define SMEM_BYTES ((SBB + 2 * SAB) * 2)   // 163840 B

__global__ __launch_bounds__(512, 1)
void gemm_kernel(const float* __restrict__ bias,
                 const float* __restrict__ pos,
                 float* __restrict__ out) {
    extern __shared__ __half sm[];
    __half* sB = sm;                   // [128][128] swizzled rows
    __half* sA0 = sm + SBB;
    __half* sA1 = sA0 + SAB;
    __shared__ __align__(8) unsigned long long bars[3];  // B, A0, A1

    const int tid  = threadIdx.x;
    const int lane = tid & 31;
    const int wid  = tid >> 5;         // 0..15
    const int grp  = lane >> 2;        // 0..7
    const int tg   = lane & 3;         // 0..3
    const int wm   = wid & 3;          // m-quarter  -> wm*64
    const int wn   = wid >> 2;         // e-quarter  -> wn*32

    const int e0 = blockIdx.x * ET;
    const int j0 = blockIdx.y * TILES;

    const uint32_t barB  = smem_u32(&bars[0]);
    const uint32_t barA0 = smem_u32(&bars[1]);
    const uint32_t barA1 = smem_u32(&bars[2]);

    if (tid == 0) {
        MBAR_INIT(barB, 1);
        MBAR_INIT(barA0, 1);
        MBAR_INIT(barA1, 1);
    }
    __syncthreads();

    if (tid == 0) {
        MBAR_EXPECT_TX(barB, SBB * 2);
        bulk_g2s(smem_u32(sB), g_B + (size_t)e0 * KP_, SBB * 2, barB);
        MBAR_EXPECT_TX(barA0, ATILE_BYTES);
        bulk_g2s(smem_u32(sA0), g_A + (size_t)j0 * MT * KP_, ATILE_BYTES, barA0);
        MBAR_EXPECT_TX(barA1, ATILE_BYTES);
        bulk_g2s(smem_u32(sA1), g_A + (size_t)(j0 + 1) * MT * KP_, ATILE_BYTES, barA1);
    }

    // ldmatrix per-lane address components
    const int aql  = lane & 7;
    const int aqm  = ((lane >> 3) & 1) * 8;
    const int akc  = lane >> 4;                  // A k8-chunk 0/1
    const uint32_t arl16 = (uint32_t)aql << 4;
    // B x4: rows nf2*16 + {0..7|8..15}, k-chunks 0/1 (covers 2 nf per load)
    const uint32_t uB4 = smem_u32(sB) +
        (uint32_t)(wn * 32 + ((lane >> 4) & 1) * 8 + (lane & 7)) * (KP_ * 2);
    const int bkc4 = (lane >> 3) & 1;
    const uint32_t brl16 = (uint32_t)(lane & 7) << 4;

    // bias is tile-invariant for this warp: hoist out of the tile loop
    const int colb = e0 + wn * 32 + tg * 2;
    float2 bb[4];
#pragma unroll
    for (int nf = 0; nf < 4; ++nf)
        bb[nf] = *(const float2*)(bias + colb + nf * 8);

    MBAR_WAIT(barB, 0);

#pragma unroll 1
    for (int i = 0; i < TILES; ++i) {
        const int buf = i & 1;
        const uint32_t barA = buf ? barA1 : barA0;
        __half* sA = buf ? sA1 : sA0;
        MBAR_WAIT(barA, (i >> 1) & 1);

        const int m0 = (j0 + i) * MT;
        const int n0 = m0 % NTOK_;
        const uint32_t uA = smem_u32(sA) +
            (uint32_t)(wm * 64 + aqm + aql) * (KP_ * 2);

        float4 acc[4][4];
#pragma unroll
        for (int a = 0; a < 4; ++a)
#pragma unroll
            for (int b = 0; b < 4; ++b) acc[a][b] = make_float4(0.f, 0.f, 0.f, 0.f);

#pragma unroll
        for (int ks = 0; ks < KSTEPS; ++ks) {
            const uint32_t offA = (uint32_t)((2 * ks + akc) << 4) ^ arl16;
            const uint32_t offB = (uint32_t)((2 * ks + bkc4) << 4) ^ brl16;

            uint32_t af[4][4], bf[4][2];
#pragma unroll
            for (int mf = 0; mf < 4; ++mf)
                ldsm_x4(af[mf], uA + (uint32_t)mf * (16 * KP_ * 2) + offA);
#pragma unroll
            for (int nf2 = 0; nf2 < 2; ++nf2) {
                uint32_t r4[4];
                ldsm_x4(r4, uB4 + (uint32_t)nf2 * (16 * KP_ * 2) + offB);
                bf[nf2 * 2][0]     = r4[0];
                bf[nf2 * 2][1]     = r4[1];
                bf[nf2 * 2 + 1][0] = r4[2];
                bf[nf2 * 2 + 1][1] = r4[3];
            }
#pragma unroll
            for (int mf = 0; mf < 4; ++mf)
#pragma unroll
                for (int nf = 0; nf < 4; ++nf)
                    mma_f16(acc[mf][nf], af[mf], bf[nf]);
        }

        // epilogue: out = acc + bias + pos (direct float2 stores)
#pragma unroll
        for (int mf = 0; mf < 4; ++mf) {
            int rl = wm * 64 + mf * 16 + grp;
            int m  = m0 + rl;
            int n  = n0 + rl;      if (n  >= NTOK_) n  -= NTOK_;
            int n2 = n0 + rl + 8;  if (n2 >= NTOK_) n2 -= NTOK_;
            const float* pr0 = pos + (size_t)n  * E_ + colb;
            const float* pr1 = pos + (size_t)n2 * E_ + colb;
            float* or0 = out + (size_t)m * E_ + colb;
            float* or1 = or0 + 8 * E_;
#pragma unroll
            for (int nf = 0; nf < 4; ++nf) {
                float2 p0 = *(const float2*)(pr0 + nf * 8);
                float2 p1 = *(const float2*)(pr1 + nf * 8);
                float4 a  = acc[mf][nf];
                float2 o0 = make_float2(a.x + bb[nf].x + p0.x, a.y + bb[nf].y + p0.y);
                float2 o1 = make_float2(a.z + bb[nf].x + p1.x, a.w + bb[nf].y + p1.y);
                __stcs((float2*)(or0 + nf * 8), o0);
                __stcs((float2*)(or1 + nf * 8), o1);
            }
        }

        // all reads of buffer `buf` done -> refill it 2 tiles ahead
        __syncthreads();
        if (tid == 0 && i + 2 < TILES) {
            MBAR_EXPECT_TX(barA, ATILE_BYTES);
            bulk_g2s(smem_u32(sA), g_A + (size_t)(j0 + i + 2) * MT * KP_,
                     ATILE_BYTES, barA);
        }
    }
}

// ---------------------------------------------------------------- launch
extern "C" void kernel_launch(void* const* d_in, const int* in_sizes, int n_in,
                              void* d_out, int out_size) {
    const float* video = (const float*)d_in[0];   // [64,16,1,84,84]
    const float* W     = (const float*)d_in[1];   // [1024,98]
    const float* bias  = (const float*)d_in[2];   // [1024]
    const float* pos   = (const float*)d_in[3];   // [1,1152,1024]
    float* out         = (float*)d_out;           // [64,1152,1024]

    cudaFuncSetAttribute(gemm_kernel, cudaFuncAttributeMaxDynamicSharedMemorySize,
                         SMEM_BYTES);
    cudaFuncSetAttribute(prep_kernel, cudaFuncAttributeMaxDynamicSharedMemorySize,
                         2 * GHALF * 2);

    prep_kernel<<<1024 + 32, 256, 2 * GHALF * 2>>>(video, W);
    gemm_kernel<<<dim3(E_ / ET, M_ / (MT * TILES)), 512, SMEM_BYTES>>>(bias, pos, out);
}